// round 2
// baseline (speedup 1.0000x reference)
#include <cuda_runtime.h>
#include <math.h>

#define Bn   16
#define Cn   768
#define Sn   729
#define Hn   8
#define Dn   96
#define En   3
#define HIDn 3072
#define NTOK (Bn*Sn)            /* 11664 tokens */
#define PERMSZ (NTOK + 64*En)   /* padded routing buffer */

// ---------------- static scratch (no allocation allowed) ----------------
__device__ float g_tok   [NTOK*Cn];                 // LN'd tokens [t, c]
__device__ float g_qkv   [(size_t)NTOK*3*Cn];       // [t, 3*C]
__device__ float g_scores[(size_t)Bn*Hn*Sn*Sn];     // attention logits/probs
__device__ float g_ctx   [NTOK*Cn];                 // attention context [t, c]
__device__ float g_tok2  [NTOK*Cn];                 // x2 tokens [t, c]
__device__ float g_h1    [(size_t)PERMSZ*HIDn];     // expert hidden
__device__ float g_mg    [NTOK];
__device__ int   g_eid   [NTOK];
__device__ float g_gscale[NTOK];
__device__ float g_denom [Sn*En];
__device__ int   g_perm  [PERMSZ];
__device__ int   g_count [En];
__device__ int   g_seg   [En+1];
__device__ int   g_pos   [En];
__device__ double g_part [Bn*64*2];
__device__ float g_mu[Bn], g_rsig[Bn];

// ---------------- LayerNorm stats ----------------
__global__ void ln_partial(const float* __restrict__ x) {
    int b = blockIdx.y, p = blockIdx.x;
    const int N = Cn*Sn;          // 559872
    const int chunk = N / 64;     // 8748 exact
    const float* xb = x + (size_t)b*N;
    double s = 0.0, ss = 0.0;
    for (int i = p*chunk + threadIdx.x; i < (p+1)*chunk; i += 256) {
        float v = xb[i];
        s += v; ss += (double)v*v;
    }
    __shared__ double sh[256], sh2[256];
    sh[threadIdx.x] = s; sh2[threadIdx.x] = ss;
    __syncthreads();
    for (int o = 128; o > 0; o >>= 1) {
        if (threadIdx.x < o) { sh[threadIdx.x] += sh[threadIdx.x+o]; sh2[threadIdx.x] += sh2[threadIdx.x+o]; }
        __syncthreads();
    }
    if (threadIdx.x == 0) {
        g_part[(b*64+p)*2]   = sh[0];
        g_part[(b*64+p)*2+1] = sh2[0];
    }
}

__global__ void ln_final() {
    int b = blockIdx.x;
    __shared__ double sh[64], sh2[64];
    sh[threadIdx.x]  = g_part[(b*64+threadIdx.x)*2];
    sh2[threadIdx.x] = g_part[(b*64+threadIdx.x)*2+1];
    __syncthreads();
    for (int o = 32; o > 0; o >>= 1) {
        if (threadIdx.x < o) { sh[threadIdx.x] += sh[threadIdx.x+o]; sh2[threadIdx.x] += sh2[threadIdx.x+o]; }
        __syncthreads();
    }
    if (threadIdx.x == 0) {
        double N  = (double)(Cn*Sn);
        double mu = sh[0]/N;
        double var = sh2[0]/N - mu*mu;
        g_mu[b]   = (float)mu;
        g_rsig[b] = (float)(1.0/sqrt(var + 1e-5));
    }
}

// normalize + affine + transpose [b,c,s] -> token-major [t,c]
__global__ void build_tok(const float* __restrict__ x,
                          const float* __restrict__ gamma,
                          const float* __restrict__ beta) {
    int idx = blockIdx.x*256 + threadIdx.x;
    if (idx >= NTOK*Cn) return;
    int c = idx % Cn, t = idx / Cn;
    int b = t / Sn, s = t % Sn;
    float v = x[((size_t)b*Cn + c)*Sn + s];
    v = (v - g_mu[b]) * g_rsig[b] * gamma[c*Sn + s] + beta[c*Sn + s];
    g_tok[idx] = v;
}

// ---------------- generic 64x64x16 fp32 GEMM tile ----------------
template<class FA, class FB, class FC>
__device__ __forceinline__ void gemm64(int M, int N, int K, int m0, int n0,
                                       FA fa, FB fb, FC fc) {
    __shared__ float As[16][68];   // [k][m], 16B-aligned rows for float4 reads
    __shared__ float Bs[16][68];   // [k][n]
    const int tid = threadIdx.x;
    const int tx = tid & 15, ty = tid >> 4;
    float acc[4][4] = {};
    for (int k0 = 0; k0 < K; k0 += 16) {
        #pragma unroll
        for (int i = 0; i < 4; i++) {
            int lin = tid + i*256;
            int m = lin >> 4, k = lin & 15;
            As[k][m] = (m0+m < M && k0+k < K) ? fa(m0+m, k0+k) : 0.f;
        }
        #pragma unroll
        for (int i = 0; i < 4; i++) {
            int lin = tid + i*256;
            int k = lin >> 6, n = lin & 63;
            Bs[k][n] = (n0+n < N && k0+k < K) ? fb(k0+k, n0+n) : 0.f;
        }
        __syncthreads();
        #pragma unroll
        for (int kk = 0; kk < 16; kk++) {
            float4 av = *(const float4*)&As[kk][ty*4];
            float4 bv = *(const float4*)&Bs[kk][tx*4];
            float a[4] = {av.x, av.y, av.z, av.w};
            float bb[4] = {bv.x, bv.y, bv.z, bv.w};
            #pragma unroll
            for (int i = 0; i < 4; i++)
                #pragma unroll
                for (int j = 0; j < 4; j++)
                    acc[i][j] = fmaf(a[i], bb[j], acc[i][j]);
        }
        __syncthreads();
    }
    #pragma unroll
    for (int i = 0; i < 4; i++)
        #pragma unroll
        for (int j = 0; j < 4; j++) {
            int m = m0 + ty*4 + i, n = n0 + tx*4 + j;
            if (m < M && n < N) fc(m, n, acc[i][j]);
        }
}

// ---------------- attention ----------------
__global__ void k_gemm_qkv(const float* __restrict__ w) {
    gemm64(NTOK, 3*Cn, Cn, blockIdx.y*64, blockIdx.x*64,
        [&] (int m, int k) { return g_tok[(size_t)m*Cn + k]; },
        [&] (int k, int n) { return w[(size_t)k*3*Cn + n]; },
        [&] (int m, int n, float v) { g_qkv[(size_t)m*3*Cn + n] = v; });
}

__global__ void k_gemm_scores() {
    int z = blockIdx.z, bI = z >> 3, h = z & 7;
    const float* qb = g_qkv + (size_t)bI*Sn*(3*Cn) + h*Dn;
    const float* kb = qb + Cn;
    float* out = g_scores + (size_t)z*Sn*Sn;
    gemm64(Sn, Sn, Dn, blockIdx.y*64, blockIdx.x*64,
        [&] (int m, int k) { return qb[(size_t)m*(3*Cn) + k]; },
        [&] (int k, int n) { return kb[(size_t)n*(3*Cn) + k]; },
        [&] (int m, int n, float v) { out[m*Sn + n] = v; });
}

__global__ void k_softmax() {
    float* p = g_scores + (size_t)blockIdx.x*Sn;
    int tid = threadIdx.x;
    __shared__ float red[128];
    float mx = -1e30f;
    for (int i = tid; i < Sn; i += 128) mx = fmaxf(mx, p[i]);
    red[tid] = mx; __syncthreads();
    for (int o = 64; o > 0; o >>= 1) { if (tid < o) red[tid] = fmaxf(red[tid], red[tid+o]); __syncthreads(); }
    mx = red[0]; __syncthreads();
    float s = 0.f;
    for (int i = tid; i < Sn; i += 128) { float e = __expf(p[i]-mx); p[i] = e; s += e; }
    red[tid] = s; __syncthreads();
    for (int o = 64; o > 0; o >>= 1) { if (tid < o) red[tid] += red[tid+o]; __syncthreads(); }
    float inv = 1.f/red[0];
    for (int i = tid; i < Sn; i += 128) p[i] *= inv;
}

__global__ void k_gemm_ctx() {
    int z = blockIdx.z, bI = z >> 3, h = z & 7;
    const float* att = g_scores + (size_t)z*Sn*Sn;
    const float* vb  = g_qkv + (size_t)bI*Sn*(3*Cn) + 2*Cn + h*Dn;
    gemm64(Sn, Dn, Sn, blockIdx.y*64, blockIdx.x*64,
        [&] (int m, int k) { return att[m*Sn + k]; },
        [&] (int k, int n) { return vb[(size_t)k*(3*Cn) + n]; },
        [&] (int m, int n, float v) {
            g_ctx[((size_t)(bI*Sn + m))*Cn + h*Dn + n] = v;
        });
}

// out-proj + residual: writes tok2 (token-major) and out = x2 ([b,c,s])
__global__ void k_gemm_wout(const float* __restrict__ w,
                            const float* __restrict__ x,
                            float* __restrict__ out) {
    gemm64(NTOK, Cn, Cn, blockIdx.y*64, blockIdx.x*64,
        [&] (int m, int k) { return g_ctx[(size_t)m*Cn + k]; },
        [&] (int k, int n) { return w[(size_t)k*Cn + n]; },
        [&] (int m, int n, float v) {
            int b = m / Sn, s = m % Sn;
            size_t oi = ((size_t)b*Cn + n)*Sn + s;
            float x2 = x[oi] + v;
            g_tok2[(size_t)m*Cn + n] = x2;
            out[oi] = x2;
        });
}

// ---------------- MoE gate + routing ----------------
__global__ void k_gate(const float* __restrict__ wg, const float* __restrict__ bg) {
    int warp = (blockIdx.x*128 + threadIdx.x) >> 5;
    int lane = threadIdx.x & 31;
    if (warp >= NTOK) return;
    const float* row = g_tok2 + (size_t)warp*Cn;
    float a0 = 0.f, a1 = 0.f, a2 = 0.f;
    for (int c = lane; c < Cn; c += 32) {
        float t = row[c];
        a0 = fmaf(t, wg[c*3+0], a0);
        a1 = fmaf(t, wg[c*3+1], a1);
        a2 = fmaf(t, wg[c*3+2], a2);
    }
    for (int o = 16; o > 0; o >>= 1) {
        a0 += __shfl_down_sync(0xffffffffu, a0, o);
        a1 += __shfl_down_sync(0xffffffffu, a1, o);
        a2 += __shfl_down_sync(0xffffffffu, a2, o);
    }
    if (lane == 0) {
        a0 += bg[0]; a1 += bg[1]; a2 += bg[2];
        int e = 0; float best = a0;                 // first-max ties like jnp.argmax
        if (a1 > best) { best = a1; e = 1; }
        if (a2 > best) { best = a2; e = 2; }
        float e0 = __expf(a0-best), e1 = __expf(a1-best), e2 = __expf(a2-best);
        float sum = e0 + e1 + e2;
        float pe = (e == 0 ? e0 : (e == 1 ? e1 : e2)) / sum;
        g_eid[warp] = e; g_mg[warp] = pe;
    }
}

__global__ void k_denom() {   // denom[s,e] = sum_b mg (deterministic)
    int i = blockIdx.x*128 + threadIdx.x;
    if (i >= Sn*En) return;
    int s = i / En, e = i % En;
    float acc = 0.f;
    for (int b = 0; b < Bn; b++) { int t = b*Sn + s; if (g_eid[t] == e) acc += g_mg[t]; }
    g_denom[i] = acc + 1e-6f;
}

__global__ void k_scale() {
    int t = blockIdx.x*256 + threadIdx.x;
    if (t >= NTOK) return;
    int s = t % Sn;
    g_gscale[t] = g_mg[t] / g_denom[s*En + g_eid[t]] * (float)Bn;
}

__global__ void k_rinit() {
    int i = blockIdx.x*256 + threadIdx.x;
    if (i < PERMSZ) g_perm[i] = -1;
    if (i < En) { g_count[i] = 0; g_pos[i] = 0; }
}
__global__ void k_rcount() {
    int t = blockIdx.x*256 + threadIdx.x;
    if (t < NTOK) atomicAdd(&g_count[g_eid[t]], 1);
}
__global__ void k_roffs() {
    int a = 0;
    for (int e = 0; e < En; e++) { g_seg[e] = a; a += (g_count[e] + 63) & ~63; }
    g_seg[En] = a;
}
__global__ void k_rscatter() {
    int t = blockIdx.x*256 + threadIdx.x;
    if (t >= NTOK) return;
    int e = g_eid[t];
    int p = atomicAdd(&g_pos[e], 1);
    g_perm[g_seg[e] + p] = t;
}

// ---------------- routed expert FFN ----------------
__global__ void k_ffn1(const float* __restrict__ w1, const float* __restrict__ b1) {
    int e = blockIdx.z;
    int cnt = g_count[e];
    int m0 = blockIdx.y*64;
    if (m0 >= cnt) return;
    int base = g_seg[e];
    const float* W = w1 + (size_t)e*Cn*HIDn;
    const float* bias = b1 + e*HIDn;
    gemm64(cnt, HIDn, Cn, m0, blockIdx.x*64,
        [&] (int m, int k) { return g_tok2[(size_t)g_perm[base+m]*Cn + k]; },
        [&] (int k, int n) { return W[(size_t)k*HIDn + n]; },
        [&] (int m, int n, float v) {
            float u = v + bias[n];
            g_h1[(size_t)(base+m)*HIDn + n] = 0.5f*u*(1.f + erff(u*0.70710678118654752f));
        });
}

__global__ void k_ffn2(const float* __restrict__ w2, const float* __restrict__ b2,
                       float* __restrict__ out) {
    int e = blockIdx.z;
    int cnt = g_count[e];
    int m0 = blockIdx.y*64;
    if (m0 >= cnt) return;
    int base = g_seg[e];
    const float* W = w2 + (size_t)e*HIDn*Cn;
    const float* bias = b2 + e*Cn;
    gemm64(cnt, Cn, HIDn, m0, blockIdx.x*64,
        [&] (int m, int k) { return g_h1[(size_t)(base+m)*HIDn + k]; },
        [&] (int k, int n) { return W[(size_t)k*Cn + n]; },
        [&] (int m, int n, float v) {
            int t = g_perm[base+m];
            float g = g_gscale[t];
            int b = t / Sn, s = t % Sn;
            size_t oi = ((size_t)b*Cn + n)*Sn + s;
            out[oi] += g * (v + bias[n]);           // out already holds x2
        });
}

// ---------------- launch ----------------
extern "C" void kernel_launch(void* const* d_in, const int* in_sizes, int n_in,
                              void* d_out, int out_size) {
    (void)in_sizes; (void)n_in; (void)out_size;
    const float* x      = (const float*)d_in[0];
    const float* gamma  = (const float*)d_in[1];
    const float* beta   = (const float*)d_in[2];
    const float* w_qkv  = (const float*)d_in[3];
    const float* w_out  = (const float*)d_in[4];
    const float* w_gate = (const float*)d_in[5];
    const float* b_gate = (const float*)d_in[6];
    const float* w1     = (const float*)d_in[7];
    const float* b1     = (const float*)d_in[8];
    const float* w2     = (const float*)d_in[9];
    const float* b2     = (const float*)d_in[10];
    float* out = (float*)d_out;

    ln_partial<<<dim3(64, Bn), 256>>>(x);
    ln_final<<<Bn, 64>>>();
    build_tok<<<(NTOK*Cn + 255)/256, 256>>>(x, gamma, beta);

    k_gemm_qkv<<<dim3((3*Cn)/64, (NTOK+63)/64), 256>>>(w_qkv);          // 36 x 183
    k_gemm_scores<<<dim3(12, 12, Bn*Hn), 256>>>();
    k_softmax<<<Bn*Hn*Sn, 128>>>();
    k_gemm_ctx<<<dim3(2, 12, Bn*Hn), 256>>>();
    k_gemm_wout<<<dim3(Cn/64, (NTOK+63)/64), 256>>>(w_out, x, out);     // 12 x 183

    k_gate<<<(NTOK + 3)/4, 128>>>(w_gate, b_gate);
    k_denom<<<(Sn*En + 127)/128, 128>>>();
    k_scale<<<(NTOK + 255)/256, 256>>>();
    k_rinit<<<(PERMSZ + 255)/256, 256>>>();
    k_rcount<<<(NTOK + 255)/256, 256>>>();
    k_roffs<<<1, 1>>>();
    k_rscatter<<<(NTOK + 255)/256, 256>>>();

    k_ffn1<<<dim3(HIDn/64, (NTOK+63)/64, En), 256>>>(w1, b1);           // 48 x 183 x 3
    k_ffn2<<<dim3(Cn/64, (NTOK+63)/64, En), 256>>>(w2, b2, out);        // 12 x 183 x 3
}

// round 4
// speedup vs baseline: 1.0926x; 1.0926x over previous
#include <cuda_runtime.h>
#include <math.h>

#define Bn   16
#define Cn   768
#define Sn   729
#define Hn   8
#define Dn   96
#define En   3
#define HIDn 3072
#define NTOK (Bn*Sn)            /* 11664 tokens */
#define PERMSZ (NTOK + 64*En)   /* padded routing buffer */

// ---------------- static scratch (no allocation allowed) ----------------
__device__ float g_tok   [NTOK*Cn];                 // LN'd tokens [t, c]
__device__ float g_qkv   [(size_t)NTOK*3*Cn];       // [t, 3*C]
__device__ float g_scores[(size_t)Bn*Hn*Sn*Sn];     // attention logits/probs
__device__ float g_ctx   [NTOK*Cn];                 // attention context [t, c]
__device__ float g_tok2  [NTOK*Cn];                 // x2 tokens [t, c]
__device__ float g_h1    [(size_t)PERMSZ*HIDn];     // expert hidden
__device__ float g_mg    [NTOK];
__device__ int   g_eid   [NTOK];
__device__ float g_gscale[NTOK];
__device__ float g_denom [Sn*En];
__device__ int   g_perm  [PERMSZ];
__device__ int   g_count [En];
__device__ int   g_seg   [En+1];
__device__ int   g_pos   [En];
__device__ double g_part [Bn*64*2];
__device__ float g_mu[Bn], g_rsig[Bn];

// ---------------- LayerNorm stats ----------------
__global__ void ln_partial(const float* __restrict__ x) {
    int b = blockIdx.y, p = blockIdx.x;
    const int N = Cn*Sn;          // 559872
    const int chunk = N / 64;     // 8748 exact
    const float* xb = x + (size_t)b*N;
    double s = 0.0, ss = 0.0;
    for (int i = p*chunk + threadIdx.x; i < (p+1)*chunk; i += 256) {
        float v = xb[i];
        s += v; ss += (double)v*v;
    }
    __shared__ double sh[256], sh2[256];
    sh[threadIdx.x] = s; sh2[threadIdx.x] = ss;
    __syncthreads();
    for (int o = 128; o > 0; o >>= 1) {
        if (threadIdx.x < o) { sh[threadIdx.x] += sh[threadIdx.x+o]; sh2[threadIdx.x] += sh2[threadIdx.x+o]; }
        __syncthreads();
    }
    if (threadIdx.x == 0) {
        g_part[(b*64+p)*2]   = sh[0];
        g_part[(b*64+p)*2+1] = sh2[0];
    }
}

__global__ void ln_final() {
    int b = blockIdx.x;
    __shared__ double sh[64], sh2[64];
    sh[threadIdx.x]  = g_part[(b*64+threadIdx.x)*2];
    sh2[threadIdx.x] = g_part[(b*64+threadIdx.x)*2+1];
    __syncthreads();
    for (int o = 32; o > 0; o >>= 1) {
        if (threadIdx.x < o) { sh[threadIdx.x] += sh[threadIdx.x+o]; sh2[threadIdx.x] += sh2[threadIdx.x+o]; }
        __syncthreads();
    }
    if (threadIdx.x == 0) {
        double N  = (double)(Cn*Sn);
        double mu = sh[0]/N;
        double var = sh2[0]/N - mu*mu;
        g_mu[b]   = (float)mu;
        g_rsig[b] = (float)(1.0/sqrt(var + 1e-5));
    }
}

// normalize + affine + transpose [b,c,s] -> token-major [t,c] via 32x32 smem tiles
__global__ void build_tok(const float* __restrict__ x,
                          const float* __restrict__ gamma,
                          const float* __restrict__ beta) {
    __shared__ float tx_[32][33], tg[32][33], tb[32][33];
    int b  = blockIdx.z;
    int c0 = blockIdx.y * 32;
    int s0 = blockIdx.x * 32;
    int li = threadIdx.x & 31;      // along s on read
    int lj = threadIdx.x >> 5;      // 0..7
    // read coalesced along s
    #pragma unroll
    for (int r = 0; r < 4; r++) {
        int c = c0 + lj + r*8;
        int s = s0 + li;
        bool ok = (s < Sn);
        size_t xi = ((size_t)b*Cn + c)*Sn + s;
        size_t gi = (size_t)c*Sn + s;
        tx_[lj + r*8][li] = ok ? x[xi] : 0.f;
        tg [lj + r*8][li] = ok ? gamma[gi] : 0.f;
        tb [lj + r*8][li] = ok ? beta[gi]  : 0.f;
    }
    __syncthreads();
    float mu = g_mu[b], rs = g_rsig[b];
    // write coalesced along c
    #pragma unroll
    for (int r = 0; r < 4; r++) {
        int s = s0 + lj + r*8;
        int c = c0 + li;
        if (s < Sn) {
            float v = (tx_[li][lj + r*8] - mu) * rs * tg[li][lj + r*8] + tb[li][lj + r*8];
            g_tok[(size_t)(b*Sn + s)*Cn + c] = v;
        }
    }
}

// ---------------- big fp32 GEMM tile: BMxBN, TMxTN microtile, reg-staged pipeline ----------------
template<int BM, int BN, int BK, int TM, int TN, int NTHR, class FA, class FB, class FC>
__device__ __forceinline__ void gemm_tile(int M, int N, int K, int m0, int n0,
                                          FA fa, FB fb, FC fc) {
    __shared__ float As[BK][BM+4];
    __shared__ float Bs[BK][BN+4];
    const int tid = threadIdx.x;
    const int tx = tid % (BN/TN);
    const int ty = tid / (BN/TN);
    constexpr int AE = (BM*BK + NTHR-1)/NTHR;
    constexpr int BE = (BN*BK + NTHR-1)/NTHR;
    float ra[AE], rb[BE];

    auto loadA = [&](int k0) {
        #pragma unroll
        for (int i = 0; i < AE; i++) {
            int idx = tid + i*NTHR;
            int m = idx / BK, k = idx % BK;
            bool ok = (idx < BM*BK) && (m0+m) < M && (k0+k) < K;
            ra[i] = ok ? fa(m0+m, k0+k) : 0.f;
        }
    };
    auto loadB = [&](int k0) {
        #pragma unroll
        for (int i = 0; i < BE; i++) {
            int idx = tid + i*NTHR;
            int k = idx / BN, n = idx % BN;
            bool ok = (idx < BK*BN) && (n0+n) < N && (k0+k) < K;
            rb[i] = ok ? fb(k0+k, n0+n) : 0.f;
        }
    };
    auto storeAB = [&]() {
        #pragma unroll
        for (int i = 0; i < AE; i++) {
            int idx = tid + i*NTHR;
            if (idx < BM*BK) As[idx % BK][idx / BK] = ra[i];
        }
        #pragma unroll
        for (int i = 0; i < BE; i++) {
            int idx = tid + i*NTHR;
            if (idx < BK*BN) Bs[idx / BN][idx % BN] = rb[i];
        }
    };

    float acc[TM][TN] = {};
    loadA(0); loadB(0);
    for (int k0 = 0; k0 < K; k0 += BK) {
        storeAB();
        __syncthreads();
        if (k0 + BK < K) { loadA(k0 + BK); loadB(k0 + BK); }
        #pragma unroll
        for (int kk = 0; kk < BK; kk++) {
            float a[TM], b[TN];
            #pragma unroll
            for (int i = 0; i < TM; i += 4) {
                float4 v = *(const float4*)&As[kk][ty*TM + i];
                a[i] = v.x; a[i+1] = v.y; a[i+2] = v.z; a[i+3] = v.w;
            }
            #pragma unroll
            for (int j = 0; j < TN; j += 4) {
                float4 v = *(const float4*)&Bs[kk][tx*TN + j];
                b[j] = v.x; b[j+1] = v.y; b[j+2] = v.z; b[j+3] = v.w;
            }
            #pragma unroll
            for (int i = 0; i < TM; i++)
                #pragma unroll
                for (int j = 0; j < TN; j++)
                    acc[i][j] = fmaf(a[i], b[j], acc[i][j]);
        }
        __syncthreads();
    }
    #pragma unroll
    for (int i = 0; i < TM; i++) {
        int m = m0 + ty*TM + i;
        if (m >= M) continue;
        #pragma unroll
        for (int j = 0; j < TN; j++) {
            int n = n0 + tx*TN + j;
            if (n < N) fc(m, n, acc[i][j]);
        }
    }
}

// ---------------- attention ----------------
__global__ void __launch_bounds__(256, 2) k_gemm_qkv(const float* __restrict__ w) {
    gemm_tile<128,128,16,8,8,256>(NTOK, 3*Cn, Cn, blockIdx.y*128, blockIdx.x*128,
        [&] (int m, int k) { return g_tok[(size_t)m*Cn + k]; },
        [&] (int k, int n) { return w[(size_t)k*3*Cn + n]; },
        [&] (int m, int n, float v) { g_qkv[(size_t)m*3*Cn + n] = v; });
}

__global__ void __launch_bounds__(256, 2) k_gemm_scores() {
    int z = blockIdx.z, bI = z >> 3, h = z & 7;
    const float* qb = g_qkv + (size_t)bI*Sn*(3*Cn) + h*Dn;
    const float* kb = qb + Cn;
    float* out = g_scores + (size_t)z*Sn*Sn;
    gemm_tile<128,128,16,8,8,256>(Sn, Sn, Dn, blockIdx.y*128, blockIdx.x*128,
        [&] (int m, int k) { return qb[(size_t)m*(3*Cn) + k]; },
        [&] (int k, int n) { return kb[(size_t)n*(3*Cn) + k]; },
        [&] (int m, int n, float v) { out[m*Sn + n] = v; });
}

__global__ void k_softmax() {
    float* p = g_scores + (size_t)blockIdx.x*Sn;
    int tid = threadIdx.x;
    __shared__ float red[128];
    float mx = -1e30f;
    for (int i = tid; i < Sn; i += 128) mx = fmaxf(mx, p[i]);
    red[tid] = mx; __syncthreads();
    for (int o = 64; o > 0; o >>= 1) { if (tid < o) red[tid] = fmaxf(red[tid], red[tid+o]); __syncthreads(); }
    mx = red[0]; __syncthreads();
    float s = 0.f;
    for (int i = tid; i < Sn; i += 128) { float e = __expf(p[i]-mx); p[i] = e; s += e; }
    red[tid] = s; __syncthreads();
    for (int o = 64; o > 0; o >>= 1) { if (tid < o) red[tid] += red[tid+o]; __syncthreads(); }
    float inv = 1.f/red[0];
    for (int i = tid; i < Sn; i += 128) p[i] *= inv;
}

__global__ void __launch_bounds__(192, 2) k_gemm_ctx() {
    int z = blockIdx.z, bI = z >> 3, h = z & 7;
    const float* att = g_scores + (size_t)z*Sn*Sn;
    const float* vb  = g_qkv + (size_t)bI*Sn*(3*Cn) + 2*Cn + h*Dn;
    gemm_tile<128,96,16,8,8,192>(Sn, Dn, Sn, blockIdx.y*128, 0,
        [&] (int m, int k) { return att[(size_t)m*Sn + k]; },
        [&] (int k, int n) { return vb[(size_t)k*(3*Cn) + n]; },
        [&] (int m, int n, float v) {
            g_ctx[((size_t)(bI*Sn + m))*Cn + h*Dn + n] = v;
        });
}

// out-proj + residual: writes tok2 (token-major) and out = x2 ([b,c,s])
__global__ void __launch_bounds__(256, 2) k_gemm_wout(const float* __restrict__ w,
                            const float* __restrict__ x,
                            float* __restrict__ out) {
    gemm_tile<128,128,16,8,8,256>(NTOK, Cn, Cn, blockIdx.y*128, blockIdx.x*128,
        [&] (int m, int k) { return g_ctx[(size_t)m*Cn + k]; },
        [&] (int k, int n) { return w[(size_t)k*Cn + n]; },
        [&] (int m, int n, float v) {
            int b = m / Sn, s = m % Sn;
            size_t oi = ((size_t)b*Cn + n)*Sn + s;
            float x2 = x[oi] + v;
            g_tok2[(size_t)m*Cn + n] = x2;
            out[oi] = x2;
        });
}

// ---------------- MoE gate + routing ----------------
__global__ void k_gate(const float* __restrict__ wg, const float* __restrict__ bg) {
    int warp = (blockIdx.x*128 + threadIdx.x) >> 5;
    int lane = threadIdx.x & 31;
    if (warp >= NTOK) return;
    const float* row = g_tok2 + (size_t)warp*Cn;
    float a0 = 0.f, a1 = 0.f, a2 = 0.f;
    for (int c = lane; c < Cn; c += 32) {
        float t = row[c];
        a0 = fmaf(t, wg[c*3+0], a0);
        a1 = fmaf(t, wg[c*3+1], a1);
        a2 = fmaf(t, wg[c*3+2], a2);
    }
    for (int o = 16; o > 0; o >>= 1) {
        a0 += __shfl_down_sync(0xffffffffu, a0, o);
        a1 += __shfl_down_sync(0xffffffffu, a1, o);
        a2 += __shfl_down_sync(0xffffffffu, a2, o);
    }
    if (lane == 0) {
        a0 += bg[0]; a1 += bg[1]; a2 += bg[2];
        int e = 0; float best = a0;                 // first-max ties like jnp.argmax
        if (a1 > best) { best = a1; e = 1; }
        if (a2 > best) { best = a2; e = 2; }
        float e0 = __expf(a0-best), e1 = __expf(a1-best), e2 = __expf(a2-best);
        float sum = e0 + e1 + e2;
        float pe = (e == 0 ? e0 : (e == 1 ? e1 : e2)) / sum;
        g_eid[warp] = e; g_mg[warp] = pe;
    }
}

__global__ void k_denom() {   // denom[s,e] = sum_b mg (deterministic)
    int i = blockIdx.x*128 + threadIdx.x;
    if (i >= Sn*En) return;
    int s = i / En, e = i % En;
    float acc = 0.f;
    for (int b = 0; b < Bn; b++) { int t = b*Sn + s; if (g_eid[t] == e) acc += g_mg[t]; }
    g_denom[i] = acc + 1e-6f;
}

__global__ void k_scale() {
    int t = blockIdx.x*256 + threadIdx.x;
    if (t >= NTOK) return;
    int s = t % Sn;
    g_gscale[t] = g_mg[t] / g_denom[s*En + g_eid[t]] * (float)Bn;
}

__global__ void k_rinit() {
    int i = blockIdx.x*256 + threadIdx.x;
    if (i < PERMSZ) g_perm[i] = -1;
    if (i < En) { g_count[i] = 0; g_pos[i] = 0; }
}
__global__ void k_rcount() {
    int t = blockIdx.x*256 + threadIdx.x;
    if (t < NTOK) atomicAdd(&g_count[g_eid[t]], 1);
}
__global__ void k_roffs() {
    int a = 0;
    for (int e = 0; e < En; e++) { g_seg[e] = a; a += (g_count[e] + 127) & ~127; }
    g_seg[En] = a;
}
__global__ void k_rscatter() {
    int t = blockIdx.x*256 + threadIdx.x;
    if (t >= NTOK) return;
    int e = g_eid[t];
    int p = atomicAdd(&g_pos[e], 1);
    g_perm[g_seg[e] + p] = t;
}

// ---------------- routed expert FFN ----------------
__global__ void __launch_bounds__(256, 2) k_ffn1(const float* __restrict__ w1, const float* __restrict__ b1) {
    int e = blockIdx.z;
    int cnt = g_count[e];
    int m0 = blockIdx.y*128;
    if (m0 >= cnt) return;
    int base = g_seg[e];
    const float* W = w1 + (size_t)e*Cn*HIDn;
    const float* bias = b1 + e*HIDn;
    gemm_tile<128,128,16,8,8,256>(cnt, HIDn, Cn, m0, blockIdx.x*128,
        [&] (int m, int k) { return g_tok2[(size_t)g_perm[base+m]*Cn + k]; },
        [&] (int k, int n) { return W[(size_t)k*HIDn + n]; },
        [&] (int m, int n, float v) {
            float u = v + bias[n];
            g_h1[(size_t)(base+m)*HIDn + n] = 0.5f*u*(1.f + erff(u*0.70710678118654752f));
        });
}

__global__ void __launch_bounds__(256, 2) k_ffn2(const float* __restrict__ w2, const float* __restrict__ b2,
                       float* __restrict__ out) {
    int e = blockIdx.z;
    int cnt = g_count[e];
    int m0 = blockIdx.y*128;
    if (m0 >= cnt) return;
    int base = g_seg[e];
    const float* W = w2 + (size_t)e*HIDn*Cn;
    const float* bias = b2 + e*Cn;
    gemm_tile<128,128,16,8,8,256>(cnt, Cn, HIDn, m0, blockIdx.x*128,
        [&] (int m, int k) { return g_h1[(size_t)(base+m)*HIDn + k]; },
        [&] (int k, int n) { return W[(size_t)k*Cn + n]; },
        [&] (int m, int n, float v) {
            int t = g_perm[base+m];
            float g = g_gscale[t];
            int b = t / Sn, s = t % Sn;
            size_t oi = ((size_t)b*Cn + n)*Sn + s;
            out[oi] += g * (v + bias[n]);           // out already holds x2
        });
}

// ---------------- launch ----------------
extern "C" void kernel_launch(void* const* d_in, const int* in_sizes, int n_in,
                              void* d_out, int out_size) {
    (void)in_sizes; (void)n_in; (void)out_size;
    const float* x      = (const float*)d_in[0];
    const float* gamma  = (const float*)d_in[1];
    const float* beta   = (const float*)d_in[2];
    const float* w_qkv  = (const float*)d_in[3];
    const float* w_out  = (const float*)d_in[4];
    const float* w_gate = (const float*)d_in[5];
    const float* b_gate = (const float*)d_in[6];
    const float* w1     = (const float*)d_in[7];
    const float* b1     = (const float*)d_in[8];
    const float* w2     = (const float*)d_in[9];
    const float* b2     = (const float*)d_in[10];
    float* out = (float*)d_out;

    ln_partial<<<dim3(64, Bn), 256>>>(x);
    ln_final<<<Bn, 64>>>();
    build_tok<<<dim3((Sn+31)/32, Cn/32, Bn), 256>>>(x, gamma, beta);

    k_gemm_qkv<<<dim3((3*Cn)/128, (NTOK+127)/128), 256>>>(w_qkv);       // 18 x 92
    k_gemm_scores<<<dim3(6, 6, Bn*Hn), 256>>>();
    k_softmax<<<Bn*Hn*Sn, 128>>>();
    k_gemm_ctx<<<dim3(1, 6, Bn*Hn), 192>>>();
    k_gemm_wout<<<dim3(Cn/128, (NTOK+127)/128), 256>>>(w_out, x, out);  // 6 x 92

    k_gate<<<(NTOK + 3)/4, 128>>>(w_gate, b_gate);
    k_denom<<<(Sn*En + 127)/128, 128>>>();
    k_scale<<<(NTOK + 255)/256, 256>>>();
    k_rinit<<<(PERMSZ + 255)/256, 256>>>();
    k_rcount<<<(NTOK + 255)/256, 256>>>();
    k_roffs<<<1, 1>>>();
    k_rscatter<<<(NTOK + 255)/256, 256>>>();

    k_ffn1<<<dim3(HIDn/128, (NTOK+127)/128, En), 256>>>(w1, b1);        // 24 x 92 x 3
    k_ffn2<<<dim3(Cn/128, (NTOK+127)/128, En), 256>>>(w2, b2, out);     // 6 x 92 x 3
}

// round 5
// speedup vs baseline: 1.3208x; 1.2089x over previous
#include <cuda_runtime.h>
#include <math.h>
#include <stdint.h>

#define Bn   16
#define Cn   768
#define Sn   729
#define Hn   8
#define Dn   96
#define En   3
#define HIDn 3072
#define NTOK (Bn*Sn)            /* 11664 tokens */
#define PERMSZ (NTOK + 128*En)  /* padded routing buffer */

// ---------------- static scratch (no allocation allowed) ----------------
__device__ float g_tok   [NTOK*Cn];                 // LN'd tokens [t, c]
__device__ float g_qkv   [(size_t)NTOK*3*Cn];       // [t, 3*C]
__device__ float g_scores[(size_t)Bn*Hn*Sn*Sn];     // attention logits/probs
__device__ float g_ctx   [NTOK*Cn];                 // attention context [t, c]
__device__ float g_tok2  [NTOK*Cn];                 // x2 tokens [t, c]
__device__ float g_h1    [(size_t)PERMSZ*HIDn];     // expert hidden
__device__ float g_mg    [NTOK];
__device__ int   g_eid   [NTOK];
__device__ float g_gscale[NTOK];
__device__ float g_denom [Sn*En];
__device__ int   g_perm  [PERMSZ];
__device__ int   g_count [En];
__device__ int   g_seg   [En+1];
__device__ int   g_pos   [En];
__device__ double g_part [Bn*64*2];
__device__ float g_mu[Bn], g_rsig[Bn];

// ---------------- LayerNorm stats ----------------
__global__ void ln_partial(const float* __restrict__ x) {
    int b = blockIdx.y, p = blockIdx.x;
    const int N = Cn*Sn;
    const int chunk = N / 64;
    const float* xb = x + (size_t)b*N;
    double s = 0.0, ss = 0.0;
    for (int i = p*chunk + threadIdx.x; i < (p+1)*chunk; i += 256) {
        float v = xb[i];
        s += v; ss += (double)v*v;
    }
    __shared__ double sh[256], sh2[256];
    sh[threadIdx.x] = s; sh2[threadIdx.x] = ss;
    __syncthreads();
    for (int o = 128; o > 0; o >>= 1) {
        if (threadIdx.x < o) { sh[threadIdx.x] += sh[threadIdx.x+o]; sh2[threadIdx.x] += sh2[threadIdx.x+o]; }
        __syncthreads();
    }
    if (threadIdx.x == 0) {
        g_part[(b*64+p)*2]   = sh[0];
        g_part[(b*64+p)*2+1] = sh2[0];
    }
}

__global__ void ln_final() {
    int b = blockIdx.x;
    __shared__ double sh[64], sh2[64];
    sh[threadIdx.x]  = g_part[(b*64+threadIdx.x)*2];
    sh2[threadIdx.x] = g_part[(b*64+threadIdx.x)*2+1];
    __syncthreads();
    for (int o = 32; o > 0; o >>= 1) {
        if (threadIdx.x < o) { sh[threadIdx.x] += sh[threadIdx.x+o]; sh2[threadIdx.x] += sh2[threadIdx.x+o]; }
        __syncthreads();
    }
    if (threadIdx.x == 0) {
        double N  = (double)(Cn*Sn);
        double mu = sh[0]/N;
        double var = sh2[0]/N - mu*mu;
        g_mu[b]   = (float)mu;
        g_rsig[b] = (float)(1.0/sqrt(var + 1e-5));
    }
}

// normalize + affine + transpose [b,c,s] -> token-major [t,c] via 32x32 smem tiles
__global__ void build_tok(const float* __restrict__ x,
                          const float* __restrict__ gamma,
                          const float* __restrict__ beta) {
    __shared__ float tx_[32][33], tg[32][33], tb[32][33];
    int b  = blockIdx.z;
    int c0 = blockIdx.y * 32;
    int s0 = blockIdx.x * 32;
    int li = threadIdx.x & 31;
    int lj = threadIdx.x >> 5;
    #pragma unroll
    for (int r = 0; r < 4; r++) {
        int c = c0 + lj + r*8;
        int s = s0 + li;
        bool ok = (s < Sn);
        size_t xi = ((size_t)b*Cn + c)*Sn + s;
        size_t gi = (size_t)c*Sn + s;
        tx_[lj + r*8][li] = ok ? x[xi] : 0.f;
        tg [lj + r*8][li] = ok ? gamma[gi] : 0.f;
        tb [lj + r*8][li] = ok ? beta[gi]  : 0.f;
    }
    __syncthreads();
    float mu = g_mu[b], rs = g_rsig[b];
    #pragma unroll
    for (int r = 0; r < 4; r++) {
        int s = s0 + lj + r*8;
        int c = c0 + li;
        if (s < Sn) {
            float v = (tx_[li][lj + r*8] - mu) * rs * tg[li][lj + r*8] + tb[li][lj + r*8];
            g_tok[(size_t)(b*Sn + s)*Cn + c] = v;
        }
    }
}

// ---------------- tf32 helpers ----------------
__device__ __forceinline__ uint32_t f2tf(float x) {
    uint32_t r;
    asm("cvt.rna.tf32.f32 %0, %1;" : "=r"(r) : "f"(x));
    return r;
}
__device__ __forceinline__ void split_tf(float x, uint32_t& hi, uint32_t& lo) {
    asm("cvt.rna.tf32.f32 %0, %1;" : "=r"(hi) : "f"(x));
    float res = x - __uint_as_float(hi);
    asm("cvt.rna.tf32.f32 %0, %1;" : "=r"(lo) : "f"(res));
}
__device__ __forceinline__ void mma8(float* c, const uint32_t* a, const uint32_t* b) {
    asm volatile(
        "mma.sync.aligned.m16n8k8.row.col.f32.tf32.tf32.f32 "
        "{%0,%1,%2,%3}, {%4,%5,%6,%7}, {%8,%9}, {%0,%1,%2,%3};"
        : "+f"(c[0]), "+f"(c[1]), "+f"(c[2]), "+f"(c[3])
        : "r"(a[0]), "r"(a[1]), "r"(a[2]), "r"(a[3]), "r"(b[0]), "r"(b[1]));
}

// ---------------- tensor-core GEMM tile: 128x64 block, 8 warps (32x32 each) ----
// SPLIT=3 -> 3xTF32 (fp32-accurate); SPLIT=1 -> plain tf32
template<int SPLIT, class FA, class FB, class FC>
__device__ __forceinline__ void gemm_tc(int M, int N, int K, int m0, int n0,
                                        FA fa, FB fb, FC fc) {
    constexpr int BM = 128, BN = 64, BK = 16, NTHR = 256;
    __shared__ float As[BK][BM + 8];   // stride 136: k-groups land on distinct bank quads
    __shared__ float Bs[BK][BN + 8];   // stride 72
    const int tid  = threadIdx.x;
    const int wid  = tid >> 5;
    const int lane = tid & 31;
    const int mw = wid >> 1;          // 0..3 -> m base mw*32
    const int nw = wid & 1;           // 0..1 -> n base nw*32
    const int r    = lane >> 2;       // 0..7
    const int cg   = lane & 3;        // 0..3

    constexpr int AE = BM*BK/NTHR;    // 8
    constexpr int BE = BN*BK/NTHR;    // 4
    float ra[AE], rb[BE];

    auto loadA = [&](int k0) {
        #pragma unroll
        for (int i = 0; i < AE; i++) {
            int idx = tid + i*NTHR;
            int m = idx / BK, k = idx % BK;
            bool ok = (m0+m) < M && (k0+k) < K;
            ra[i] = ok ? fa(m0+m, k0+k) : 0.f;
        }
    };
    auto loadB = [&](int k0) {
        #pragma unroll
        for (int i = 0; i < BE; i++) {
            int idx = tid + i*NTHR;
            int k = idx / BN, n = idx % BN;
            bool ok = (n0+n) < N && (k0+k) < K;
            rb[i] = ok ? fb(k0+k, n0+n) : 0.f;
        }
    };
    auto storeAB = [&]() {
        #pragma unroll
        for (int i = 0; i < AE; i++) {
            int idx = tid + i*NTHR;
            As[idx % BK][idx / BK] = ra[i];
        }
        #pragma unroll
        for (int i = 0; i < BE; i++) {
            int idx = tid + i*NTHR;
            Bs[idx / BN][idx % BN] = rb[i];
        }
    };

    float acc[2][4][4];
    #pragma unroll
    for (int i = 0; i < 2; i++)
        #pragma unroll
        for (int j = 0; j < 4; j++)
            #pragma unroll
            for (int q = 0; q < 4; q++) acc[i][j][q] = 0.f;

    loadA(0); loadB(0);
    for (int k0 = 0; k0 < K; k0 += BK) {
        storeAB();
        __syncthreads();
        if (k0 + BK < K) { loadA(k0 + BK); loadB(k0 + BK); }
        #pragma unroll
        for (int ks = 0; ks < BK; ks += 8) {
            uint32_t aH[2][4], aL[2][4], bH[4][2], bL[4][2];
            #pragma unroll
            for (int i = 0; i < 2; i++) {
                int mb = mw*32 + i*16;
                float v0 = As[ks + cg    ][mb + r    ];
                float v1 = As[ks + cg    ][mb + r + 8];
                float v2 = As[ks + cg + 4][mb + r    ];
                float v3 = As[ks + cg + 4][mb + r + 8];
                if (SPLIT == 3) {
                    split_tf(v0, aH[i][0], aL[i][0]);
                    split_tf(v1, aH[i][1], aL[i][1]);
                    split_tf(v2, aH[i][2], aL[i][2]);
                    split_tf(v3, aH[i][3], aL[i][3]);
                } else {
                    aH[i][0] = f2tf(v0); aH[i][1] = f2tf(v1);
                    aH[i][2] = f2tf(v2); aH[i][3] = f2tf(v3);
                }
            }
            #pragma unroll
            for (int j = 0; j < 4; j++) {
                int nb = nw*32 + j*8;
                float v0 = Bs[ks + cg    ][nb + r];
                float v1 = Bs[ks + cg + 4][nb + r];
                if (SPLIT == 3) {
                    split_tf(v0, bH[j][0], bL[j][0]);
                    split_tf(v1, bH[j][1], bL[j][1]);
                } else {
                    bH[j][0] = f2tf(v0); bH[j][1] = f2tf(v1);
                }
            }
            #pragma unroll
            for (int i = 0; i < 2; i++)
                #pragma unroll
                for (int j = 0; j < 4; j++) {
                    if (SPLIT == 3) {
                        mma8(acc[i][j], aL[i], bH[j]);
                        mma8(acc[i][j], aH[i], bL[j]);
                    }
                    mma8(acc[i][j], aH[i], bH[j]);
                }
        }
        __syncthreads();
    }
    #pragma unroll
    for (int i = 0; i < 2; i++) {
        #pragma unroll
        for (int j = 0; j < 4; j++) {
            int mA = m0 + mw*32 + i*16 + r;
            int nA = n0 + nw*32 + j*8 + cg*2;
            if (mA < M) {
                if (nA   < N) fc(mA, nA,   acc[i][j][0]);
                if (nA+1 < N) fc(mA, nA+1, acc[i][j][1]);
            }
            if (mA + 8 < M) {
                if (nA   < N) fc(mA+8, nA,   acc[i][j][2]);
                if (nA+1 < N) fc(mA+8, nA+1, acc[i][j][3]);
            }
        }
    }
}

// ---------------- attention ----------------
__global__ void __launch_bounds__(256, 2) k_gemm_qkv(const float* __restrict__ w) {
    gemm_tc<3>(NTOK, 3*Cn, Cn, blockIdx.y*128, blockIdx.x*64,
        [&] (int m, int k) { return g_tok[(size_t)m*Cn + k]; },
        [&] (int k, int n) { return w[(size_t)k*3*Cn + n]; },
        [&] (int m, int n, float v) { g_qkv[(size_t)m*3*Cn + n] = v; });
}

__global__ void __launch_bounds__(256, 2) k_gemm_scores() {
    int z = blockIdx.z, bI = z >> 3, h = z & 7;
    const float* qb = g_qkv + (size_t)bI*Sn*(3*Cn) + h*Dn;
    const float* kb = qb + Cn;
    float* out = g_scores + (size_t)z*Sn*Sn;
    gemm_tc<3>(Sn, Sn, Dn, blockIdx.y*128, blockIdx.x*64,
        [&] (int m, int k) { return qb[(size_t)m*(3*Cn) + k]; },
        [&] (int k, int n) { return kb[(size_t)n*(3*Cn) + k]; },
        [&] (int m, int n, float v) { out[m*Sn + n] = v; });
}

__global__ void k_softmax() {
    float* p = g_scores + (size_t)blockIdx.x*Sn;
    int tid = threadIdx.x;
    __shared__ float red[128];
    float mx = -1e30f;
    for (int i = tid; i < Sn; i += 128) mx = fmaxf(mx, p[i]);
    red[tid] = mx; __syncthreads();
    for (int o = 64; o > 0; o >>= 1) { if (tid < o) red[tid] = fmaxf(red[tid], red[tid+o]); __syncthreads(); }
    mx = red[0]; __syncthreads();
    float s = 0.f;
    for (int i = tid; i < Sn; i += 128) { float e = __expf(p[i]-mx); p[i] = e; s += e; }
    red[tid] = s; __syncthreads();
    for (int o = 64; o > 0; o >>= 1) { if (tid < o) red[tid] += red[tid+o]; __syncthreads(); }
    float inv = 1.f/red[0];
    for (int i = tid; i < Sn; i += 128) p[i] *= inv;
}

__global__ void __launch_bounds__(256, 2) k_gemm_ctx() {
    int z = blockIdx.z, bI = z >> 3, h = z & 7;
    const float* att = g_scores + (size_t)z*Sn*Sn;
    const float* vb  = g_qkv + (size_t)bI*Sn*(3*Cn) + 2*Cn + h*Dn;
    gemm_tc<3>(Sn, Dn, Sn, blockIdx.y*128, blockIdx.x*64,
        [&] (int m, int k) { return att[(size_t)m*Sn + k]; },
        [&] (int k, int n) { return vb[(size_t)k*(3*Cn) + n]; },
        [&] (int m, int n, float v) {
            g_ctx[((size_t)(bI*Sn + m))*Cn + h*Dn + n] = v;
        });
}

// out-proj + residual: writes tok2 (token-major) and out = x2 ([b,c,s])
__global__ void __launch_bounds__(256, 2) k_gemm_wout(const float* __restrict__ w,
                            const float* __restrict__ x,
                            float* __restrict__ out) {
    gemm_tc<3>(NTOK, Cn, Cn, blockIdx.y*128, blockIdx.x*64,
        [&] (int m, int k) { return g_ctx[(size_t)m*Cn + k]; },
        [&] (int k, int n) { return w[(size_t)k*Cn + n]; },
        [&] (int m, int n, float v) {
            int b = m / Sn, s = m % Sn;
            size_t oi = ((size_t)b*Cn + n)*Sn + s;
            float x2 = x[oi] + v;
            g_tok2[(size_t)m*Cn + n] = x2;
            out[oi] = x2;
        });
}

// ---------------- MoE gate + routing ----------------
__global__ void k_gate(const float* __restrict__ wg, const float* __restrict__ bg) {
    int warp = (blockIdx.x*128 + threadIdx.x) >> 5;
    int lane = threadIdx.x & 31;
    if (warp >= NTOK) return;
    const float* row = g_tok2 + (size_t)warp*Cn;
    float a0 = 0.f, a1 = 0.f, a2 = 0.f;
    for (int c = lane; c < Cn; c += 32) {
        float t = row[c];
        a0 = fmaf(t, wg[c*3+0], a0);
        a1 = fmaf(t, wg[c*3+1], a1);
        a2 = fmaf(t, wg[c*3+2], a2);
    }
    for (int o = 16; o > 0; o >>= 1) {
        a0 += __shfl_down_sync(0xffffffffu, a0, o);
        a1 += __shfl_down_sync(0xffffffffu, a1, o);
        a2 += __shfl_down_sync(0xffffffffu, a2, o);
    }
    if (lane == 0) {
        a0 += bg[0]; a1 += bg[1]; a2 += bg[2];
        int e = 0; float best = a0;
        if (a1 > best) { best = a1; e = 1; }
        if (a2 > best) { best = a2; e = 2; }
        float e0 = __expf(a0-best), e1 = __expf(a1-best), e2 = __expf(a2-best);
        float sum = e0 + e1 + e2;
        float pe = (e == 0 ? e0 : (e == 1 ? e1 : e2)) / sum;
        g_eid[warp] = e; g_mg[warp] = pe;
    }
}

__global__ void k_denom() {
    int i = blockIdx.x*128 + threadIdx.x;
    if (i >= Sn*En) return;
    int s = i / En, e = i % En;
    float acc = 0.f;
    for (int b = 0; b < Bn; b++) { int t = b*Sn + s; if (g_eid[t] == e) acc += g_mg[t]; }
    g_denom[i] = acc + 1e-6f;
}

__global__ void k_scale() {
    int t = blockIdx.x*256 + threadIdx.x;
    if (t >= NTOK) return;
    int s = t % Sn;
    g_gscale[t] = g_mg[t] / g_denom[s*En + g_eid[t]] * (float)Bn;
}

__global__ void k_rinit() {
    int i = blockIdx.x*256 + threadIdx.x;
    if (i < PERMSZ) g_perm[i] = -1;
    if (i < En) { g_count[i] = 0; g_pos[i] = 0; }
}
__global__ void k_rcount() {
    int t = blockIdx.x*256 + threadIdx.x;
    if (t < NTOK) atomicAdd(&g_count[g_eid[t]], 1);
}
__global__ void k_roffs() {
    int a = 0;
    for (int e = 0; e < En; e++) { g_seg[e] = a; a += (g_count[e] + 127) & ~127; }
    g_seg[En] = a;
}
__global__ void k_rscatter() {
    int t = blockIdx.x*256 + threadIdx.x;
    if (t >= NTOK) return;
    int e = g_eid[t];
    int p = atomicAdd(&g_pos[e], 1);
    g_perm[g_seg[e] + p] = t;
}

// ---------------- routed expert FFN ----------------
__global__ void __launch_bounds__(256, 2) k_ffn1(const float* __restrict__ w1, const float* __restrict__ b1) {
    int e = blockIdx.z;
    int cnt = g_count[e];
    int m0 = blockIdx.y*128;
    if (m0 >= cnt) return;
    int base = g_seg[e];
    const float* W = w1 + (size_t)e*Cn*HIDn;
    const float* bias = b1 + e*HIDn;
    gemm_tc<3>(cnt, HIDn, Cn, m0, blockIdx.x*64,
        [&] (int m, int k) { return g_tok2[(size_t)g_perm[base+m]*Cn + k]; },
        [&] (int k, int n) { return W[(size_t)k*HIDn + n]; },
        [&] (int m, int n, float v) {
            float u = v + bias[n];
            g_h1[(size_t)(base+m)*HIDn + n] = 0.5f*u*(1.f + erff(u*0.70710678118654752f));
        });
}

__global__ void __launch_bounds__(256, 2) k_ffn2(const float* __restrict__ w2, const float* __restrict__ b2,
                       float* __restrict__ out) {
    int e = blockIdx.z;
    int cnt = g_count[e];
    int m0 = blockIdx.y*128;
    if (m0 >= cnt) return;
    int base = g_seg[e];
    const float* W = w2 + (size_t)e*HIDn*Cn;
    const float* bias = b2 + e*Cn;
    gemm_tc<3>(cnt, Cn, HIDn, m0, blockIdx.x*64,
        [&] (int m, int k) { return g_h1[(size_t)(base+m)*HIDn + k]; },
        [&] (int k, int n) { return W[(size_t)k*Cn + n]; },
        [&] (int m, int n, float v) {
            int t = g_perm[base+m];
            float g = g_gscale[t];
            int b = t / Sn, s = t % Sn;
            size_t oi = ((size_t)b*Cn + n)*Sn + s;
            out[oi] += g * (v + bias[n]);
        });
}

// ---------------- launch ----------------
extern "C" void kernel_launch(void* const* d_in, const int* in_sizes, int n_in,
                              void* d_out, int out_size) {
    (void)in_sizes; (void)n_in; (void)out_size;
    const float* x      = (const float*)d_in[0];
    const float* gamma  = (const float*)d_in[1];
    const float* beta   = (const float*)d_in[2];
    const float* w_qkv  = (const float*)d_in[3];
    const float* w_out  = (const float*)d_in[4];
    const float* w_gate = (const float*)d_in[5];
    const float* b_gate = (const float*)d_in[6];
    const float* w1     = (const float*)d_in[7];
    const float* b1     = (const float*)d_in[8];
    const float* w2     = (const float*)d_in[9];
    const float* b2     = (const float*)d_in[10];
    float* out = (float*)d_out;

    ln_partial<<<dim3(64, Bn), 256>>>(x);
    ln_final<<<Bn, 64>>>();
    build_tok<<<dim3((Sn+31)/32, Cn/32, Bn), 256>>>(x, gamma, beta);

    k_gemm_qkv<<<dim3((3*Cn)/64, (NTOK+127)/128), 256>>>(w_qkv);        // 36 x 92
    k_gemm_scores<<<dim3(12, 6, Bn*Hn), 256>>>();
    k_softmax<<<Bn*Hn*Sn, 128>>>();
    k_gemm_ctx<<<dim3(2, 6, Bn*Hn), 256>>>();
    k_gemm_wout<<<dim3(Cn/64, (NTOK+127)/128), 256>>>(w_out, x, out);   // 12 x 92

    k_gate<<<(NTOK + 3)/4, 128>>>(w_gate, b_gate);
    k_denom<<<(Sn*En + 127)/128, 128>>>();
    k_scale<<<(NTOK + 255)/256, 256>>>();
    k_rinit<<<(PERMSZ + 255)/256, 256>>>();
    k_rcount<<<(NTOK + 255)/256, 256>>>();
    k_roffs<<<1, 1>>>();
    k_rscatter<<<(NTOK + 255)/256, 256>>>();

    k_ffn1<<<dim3(HIDn/64, (NTOK+127)/128, En), 256>>>(w1, b1);         // 48 x 92 x 3
    k_ffn2<<<dim3(Cn/64, (NTOK+127)/128, En), 256>>>(w2, b2, out);      // 12 x 92 x 3
}